// round 5
// baseline (speedup 1.0000x reference)
#include <cuda_runtime.h>

#define BB 128
#define SS 512
#define KK 4
#define DD 300
#define CC 20
#define NN 10000
#define GRID 148
#define TPB 320
#define SGRP 16
#define PH1_NODES 80    // nodes per block in phase 1 (320 thr = 80 nodes x 4 cgroups)

// Persistent scratch + barrier state (state returns to reusable values each call)
__device__ float g_P[NN * CC];                  // P = node_emb @ fc_w^T (800 KB)
__device__ unsigned int g_count = 0;
__device__ volatile unsigned int g_gen = 0;

struct SmemP1 { float sF[CC * DD]; };           // 24000 B
struct SmemP2 {
    int   sX[SS];                               // 2 KB
    float sNW[SS];                              // 2 KB
    int   sNX[SS * KK];                         // 8 KB
    float sEW[SS * KK];                         // 8 KB
    float sred[SGRP][CC];                       // 1.25 KB
};
union SmemU { SmemP1 p1; SmemP2 p2; };

__device__ __forceinline__ void grid_barrier()
{
    __syncthreads();
    if (threadIdx.x == 0) {
        const unsigned gen = g_gen;             // read BEFORE arriving
        __threadfence();                        // release my phase-1 writes
        const unsigned old = atomicAdd(&g_count, 1u);
        if (old == GRID - 1) {
            g_count = 0;                        // reset for next barrier/launch
            __threadfence();                    // count reset visible before gen bump
            g_gen = gen + 1;
        } else {
            while (*(volatile unsigned*)&g_gen == gen) { }
        }
        __threadfence();                        // acquire others' writes
    }
    __syncthreads();
}

__global__ void __launch_bounds__(TPB) fused_kernel(
    const int* __restrict__ X, const int* __restrict__ NX, const int* __restrict__ EW,
    const float* __restrict__ node_emb, const float* __restrict__ edge_w,
    const float* __restrict__ node_w, const float* __restrict__ fc_w,
    const float* __restrict__ fc_b, float* __restrict__ out)
{
    __shared__ SmemU sm;
    const int t   = threadIdx.x;
    const int bid = blockIdx.x;

    // ---------------- Phase 1: P[n,c] = sum_d E[n,d] * W[c,d] ----------------
    for (int i = t; i < CC * DD; i += TPB) sm.p1.sF[i] = fc_w[i];
    __syncthreads();

    {
        const int ng = t >> 2;                  // 0..79 node within block
        const int cg = t & 3;                   // 0..3  class-group (5 classes)
        const int n  = bid * PH1_NODES + ng;
        if (n < NN) {
            const float4* __restrict__ e4 = (const float4*)(node_emb + (size_t)n * DD);
            const float*  f = sm.p1.sF + cg * 5 * DD;
            float acc[5] = {0.f, 0.f, 0.f, 0.f, 0.f};
            #pragma unroll 5
            for (int dq = 0; dq < DD / 4; dq++) {   // 75 iters: 1 LDG.128 + 5 LDS.128 + 20 FFMA
                const float4 a = e4[dq];
                #pragma unroll
                for (int c5 = 0; c5 < 5; c5++) {
                    const float4 fv = *(const float4*)(f + c5 * DD + dq * 4);
                    acc[c5] += a.x * fv.x + a.y * fv.y + a.z * fv.z + a.w * fv.w;
                }
            }
            #pragma unroll
            for (int c5 = 0; c5 < 5; c5++)
                g_P[n * CC + cg * 5 + c5] = acc[c5];
        }
    }

    grid_barrier();                             // P fully built & visible

    // ------------- Phase 2+3: per-b gather on P, reduce, softmax -------------
    if (bid >= BB) return;
    const int b = bid;

    // Stage all indices/scalars for this b: 2048 random edge_w DRAM gathers
    // issued by 320 threads -> ~7 rounds, high MLP.
    for (int i = t; i < SS; i += TPB) {
        const int x = X[b * SS + i];
        sm.p2.sX[i]  = x;
        sm.p2.sNW[i] = node_w[x];
    }
    for (int i = t; i < SS * KK; i += TPB) sm.p2.sNX[i] = NX[b * SS * KK + i];
    for (int i = t; i < SS * KK; i += TPB) sm.p2.sEW[i] = edge_w[EW[b * SS * KK + i]];
    __syncthreads();

    // thread (g, c): class c over 32 s-positions; 80B row-gathers on P (L1/L2)
    const int g = t / CC, c = t % CC;
    float acc = 0.f;
    #pragma unroll 4
    for (int i = 0; i < SS / SGRP; i++) {       // 32
        const int s = g + i * SGRP;
        const float nw = sm.p2.sNW[s];
        float m = 0.f;
        #pragma unroll
        for (int k = 0; k < KK; k++)
            m += sm.p2.sEW[s * KK + k] * g_P[sm.p2.sNX[s * KK + k] * CC + c];
        acc += (1.f - nw) * m + nw * g_P[sm.p2.sX[s] * CC + c];
    }
    sm.p2.sred[g][c] = acc;
    __syncthreads();

    // Fixed-order tree reduce over 16 s-groups -> deterministic
    #pragma unroll
    for (int off = SGRP / 2; off > 0; off >>= 1) {
        if (g < off) sm.p2.sred[g][c] += sm.p2.sred[g + off][c];
        __syncthreads();
    }

    // warp 0: bias + relu + softmax over 20 classes
    if (t < 32) {
        const float l = (t < CC) ? fmaxf(sm.p2.sred[0][t] + fc_b[t], 0.f) : -1e30f;
        float mx = l;
        #pragma unroll
        for (int o = 16; o; o >>= 1) mx = fmaxf(mx, __shfl_xor_sync(0xffffffffu, mx, o));
        const float e = (t < CC) ? __expf(l - mx) : 0.f;
        float sum = e;
        #pragma unroll
        for (int o = 16; o; o >>= 1) sum += __shfl_xor_sync(0xffffffffu, sum, o);
        if (t < CC) out[b * CC + t] = e / sum;
    }
}

extern "C" void kernel_launch(void* const* d_in, const int* in_sizes, int n_in,
                              void* d_out, int out_size)
{
    const int*   X        = (const int*)  d_in[0];
    const int*   NX       = (const int*)  d_in[1];
    const int*   EW       = (const int*)  d_in[2];
    const float* node_emb = (const float*)d_in[3];
    const float* edge_w   = (const float*)d_in[4];
    const float* node_w   = (const float*)d_in[5];
    const float* fc_w     = (const float*)d_in[6];
    const float* fc_b     = (const float*)d_in[7];
    float* out = (float*)d_out;

    fused_kernel<<<GRID, TPB>>>(X, NX, EW, node_emb, edge_w, node_w, fc_w, fc_b, out);
}

// round 6
// speedup vs baseline: 1.2989x; 1.2989x over previous
#include <cuda_runtime.h>

#define BB 128
#define SS 512
#define KK 4
#define DD 300
#define CC 20
#define NN 10000

// gather config
#define CHUNKS 2
#define SCHUNK (SS / CHUNKS)   // 256
#define SGRP 16
#define TPB (SGRP * CC)        // 320

// p_kernel tiling: thread = (node-pair, 5-class group, d-chunk of 60)
#define DSPLIT   5
#define DCH      (DD / DSPLIT)                       // 60
#define PD_TPB   128
#define PD_PAIRS 32                                  // node-pairs per block (64 nodes)
#define PD_GRIDX ((NN + 2 * PD_PAIRS - 1) / (2 * PD_PAIRS))   // 157

// Scratch (deterministic, rewritten every call)
__device__ float g_Pp[DSPLIT][NN * CC];      // split-D partials (4 MB)
__device__ float g_P[NN * CC];               // P = node_emb @ fc_w^T (800 KB)
__device__ float g_part[BB * CHUNKS * CC];   // per-(b,chunk) logit partials

// ---------------------------------------------------------------------------
// K1: split-D partial GEMM, 2 nodes x 5 classes per thread.
// 100k threads (~21 warps/SM). Per 4d: 1x2 LDG.128 + 5 LDS.128 + 40 FFMA.
// ---------------------------------------------------------------------------
__global__ void __launch_bounds__(PD_TPB) p_kernel(
    const float* __restrict__ node_emb, const float* __restrict__ fc_w)
{
    __shared__ float sF[CC * DCH];            // 4.8 KB, [c][d] chunk-contiguous

    const int t  = threadIdx.x;
    const int dc = blockIdx.y;
    const int d0 = dc * DCH;

    for (int i = t; i < CC * DCH; i += PD_TPB) {
        const int c = i / DCH, d = i % DCH;
        sF[i] = fc_w[c * DD + d0 + d];
    }
    __syncthreads();

    const int ng = t >> 2;                    // 0..31 node-pair within block
    const int cg = t & 3;                     // 0..3  class-group (5 classes)
    const int n0 = (blockIdx.x * PD_PAIRS + ng) * 2;
    if (n0 >= NN) return;                     // NN even -> pairs never split

    const float4* __restrict__ e0 = (const float4*)(node_emb + (size_t)n0 * DD + d0);
    const float4* __restrict__ e1 = (const float4*)(node_emb + (size_t)(n0 + 1) * DD + d0);
    const float4* __restrict__ f4 = (const float4*)(sF) + (cg * 5) * (DCH / 4);

    float acc0[5] = {0.f, 0.f, 0.f, 0.f, 0.f};
    float acc1[5] = {0.f, 0.f, 0.f, 0.f, 0.f};

    #pragma unroll
    for (int dq = 0; dq < DCH / 4; dq++) {    // 15 iters
        const float4 a0 = e0[dq];
        const float4 a1 = e1[dq];
        #pragma unroll
        for (int c5 = 0; c5 < 5; c5++) {
            const float4 fv = f4[c5 * (DCH / 4) + dq];
            acc0[c5] += a0.x * fv.x + a0.y * fv.y + a0.z * fv.z + a0.w * fv.w;
            acc1[c5] += a1.x * fv.x + a1.y * fv.y + a1.z * fv.z + a1.w * fv.w;
        }
    }

    #pragma unroll
    for (int c5 = 0; c5 < 5; c5++) {
        g_Pp[dc][n0 * CC + cg * 5 + c5]       = acc0[c5];
        g_Pp[dc][(n0 + 1) * CC + cg * 5 + c5] = acc1[c5];
    }
}

// ---------------------------------------------------------------------------
// K1b: reduce split-D partials (fixed order -> deterministic)
// ---------------------------------------------------------------------------
__global__ void __launch_bounds__(256) p_reduce_kernel()
{
    const int i = blockIdx.x * 256 + threadIdx.x;
    if (i < NN * CC) {
        float s = g_Pp[0][i];
        #pragma unroll
        for (int dc = 1; dc < DSPLIT; dc++) s += g_Pp[dc][i];
        g_P[i] = s;
    }
}

// ---------------------------------------------------------------------------
// K2: per-(b, s-chunk of 256) logit partials via 80B gathers on P
// ---------------------------------------------------------------------------
__global__ void __launch_bounds__(TPB) gather_kernel(
    const int* __restrict__ X, const int* __restrict__ NX, const int* __restrict__ EW,
    const float* __restrict__ edge_w, const float* __restrict__ node_w)
{
    __shared__ int   sX[SCHUNK];
    __shared__ float sNW[SCHUNK];
    __shared__ int   sNX[SCHUNK * KK];
    __shared__ float sEW[SCHUNK * KK];
    __shared__ float sred[SGRP][CC];

    const int b  = blockIdx.y;
    const int ch = blockIdx.x;
    const int s0 = ch * SCHUNK;
    const int t  = threadIdx.x;

    // Cooperative prefetch: 1024 random edge_w DRAM gathers over 320 threads
    // -> 3.2 rounds, high MLP.
    for (int i = t; i < SCHUNK; i += TPB) {
        const int x = X[b * SS + s0 + i];
        sX[i]  = x;
        sNW[i] = node_w[x];
    }
    for (int i = t; i < SCHUNK * KK; i += TPB) sNX[i] = NX[(b * SS + s0) * KK + i];
    for (int i = t; i < SCHUNK * KK; i += TPB) sEW[i] = edge_w[EW[(b * SS + s0) * KK + i]];
    __syncthreads();

    // thread (g, c): class c over 16 s-positions; 80B row-gathers on P (L2)
    const int g = t / CC, c = t % CC;
    float acc = 0.f;
    #pragma unroll 4
    for (int i = 0; i < SCHUNK / SGRP; i++) {  // 16
        const int s = g + i * SGRP;
        const float nw = sNW[s];
        float m = 0.f;
        #pragma unroll
        for (int k = 0; k < KK; k++)
            m += sEW[s * KK + k] * __ldg(&g_P[sNX[s * KK + k] * CC + c]);
        acc += (1.f - nw) * m + nw * __ldg(&g_P[sX[s] * CC + c]);
    }
    sred[g][c] = acc;
    __syncthreads();

    #pragma unroll
    for (int off = SGRP / 2; off > 0; off >>= 1) {
        if (g < off) sred[g][c] += sred[g + off][c];
        __syncthreads();
    }
    if (g == 0) g_part[(b * CHUNKS + ch) * CC + c] = sred[0][c];
}

// ---------------------------------------------------------------------------
// K3: reduce chunk partials, add bias, relu, softmax
// ---------------------------------------------------------------------------
__global__ void __launch_bounds__(32) head_kernel(
    const float* __restrict__ fc_b, float* __restrict__ out)
{
    const int b = blockIdx.x, t = threadIdx.x;

    float l = -1e30f;
    if (t < CC) {
        float s = fc_b[t];
        #pragma unroll
        for (int ch = 0; ch < CHUNKS; ch++)
            s += g_part[(b * CHUNKS + ch) * CC + t];
        l = fmaxf(s, 0.f);
    }
    float mx = l;
    #pragma unroll
    for (int o = 16; o; o >>= 1) mx = fmaxf(mx, __shfl_xor_sync(0xffffffffu, mx, o));
    const float e = (t < CC) ? __expf(l - mx) : 0.f;
    float sum = e;
    #pragma unroll
    for (int o = 16; o; o >>= 1) sum += __shfl_xor_sync(0xffffffffu, sum, o);
    if (t < CC) out[b * CC + t] = e / sum;
}

// ---------------------------------------------------------------------------
extern "C" void kernel_launch(void* const* d_in, const int* in_sizes, int n_in,
                              void* d_out, int out_size)
{
    const int*   X        = (const int*)  d_in[0];
    const int*   NX       = (const int*)  d_in[1];
    const int*   EW       = (const int*)  d_in[2];
    const float* node_emb = (const float*)d_in[3];
    const float* edge_w   = (const float*)d_in[4];
    const float* node_w   = (const float*)d_in[5];
    const float* fc_w     = (const float*)d_in[6];
    const float* fc_b     = (const float*)d_in[7];
    float* out = (float*)d_out;

    dim3 grid1(PD_GRIDX, DSPLIT);
    p_kernel<<<grid1, PD_TPB>>>(node_emb, fc_w);
    p_reduce_kernel<<<(NN * CC + 255) / 256, 256>>>();
    dim3 grid2(CHUNKS, BB);
    gather_kernel<<<grid2, TPB>>>(X, NX, EW, edge_w, node_w);
    head_kernel<<<BB, 32>>>(fc_b, out);
}